// round 7
// baseline (speedup 1.0000x reference)
#include <cuda_runtime.h>
#include <cuda_fp16.h>
#include <cstdint>

#define NPTS    16384
#define NBINS   256
#define NSLICE  16
#define SLICEN  (NPTS/NSLICE)      // 1024 targets per slice
#define TPB     256
#define QPB     256                // queries per tile
#define QT      (NPTS/QPB)         // 64 tiles per direction
#define WPB     8
#define REDB    (2*NPTS/TPB)       // 128 reduction blocks
#define XLO     (-8.0f)
#define XWIDTH  (16.0f/NBINS)

// ---- pipeline state; everything transient is re-initialized each replay ----
__device__ int      g_hist[2][NBINS];
__device__ int      g_start[2][NBINS + 1];
__device__ int      g_cursor[2][NBINS];
__device__ unsigned g_exlo[2][NSLICE], g_exhi[2][NSLICE]; // encoded slice x-ranges
__device__ float4   g_pts[2][NPTS];          // sorted (x,y,z, orig_idx bits)
__device__ uint4    g_frag[2][NPTS][2];      // target B-fragments, sorted order
__device__ unsigned g_best[2][NPTS];         // per-row best dist (encoded), atomicMin
__device__ float    g_wb[2][QT][WPB];        // per-warp seed bound
__device__ float    g_wlo[2][QT][WPB], g_whi[2][QT][WPB];
__device__ float    g_bsum[REDB];
__device__ unsigned g_ticket;

// ---- order-preserving float<->uint encode ----
static __device__ __forceinline__ unsigned enc_f(float f) {
    unsigned u = __float_as_uint(f);
    return (u & 0x80000000u) ? ~u : (u | 0x80000000u);
}
static __device__ __forceinline__ float dec_f(unsigned u) {
    unsigned b = (u & 0x80000000u) ? (u & 0x7fffffffu) : ~u;
    return __uint_as_float(b);
}
static __device__ __forceinline__ unsigned pkh2(__half lo, __half hi) {
    __half2 h = __halves2half2(lo, hi);
    return *reinterpret_cast<unsigned*>(&h);
}

// m16n8k16 fp16 MMA, fp32 accumulate. A row-major, B col-major.
#define MMA_F16(d0,d1,d2,d3, a0,a1,a2,a3, b0,b1, c0,c1,c2,c3)                       \
    asm("mma.sync.aligned.m16n8k16.row.col.f32.f16.f16.f32 "                        \
        "{%0,%1,%2,%3}, {%4,%5,%6,%7}, {%8,%9}, {%10,%11,%12,%13};"                 \
        : "=f"(d0), "=f"(d1), "=f"(d2), "=f"(d3)                                    \
        : "r"(a0), "r"(a1), "r"(a2), "r"(a3), "r"(b0), "r"(b1),                     \
          "f"(c0), "f"(c1), "f"(c2), "f"(c3))

// ============================================================================
// 1) x-histogram + per-row best init (each (dir,row) touched exactly once)
// ============================================================================
__global__ void k_hist(const float* __restrict__ adv, const float* __restrict__ ori) {
    int i = blockIdx.x * blockDim.x + threadIdx.x;
    int c = i >> 14, idx = i & (NPTS - 1);
    const float* src = c ? ori : adv;
    float x = src[3 * idx];
    int bin = min(max((int)((x - XLO) * (1.0f / XWIDTH)), 0), NBINS - 1);
    atomicAdd(&g_hist[c][bin], 1);
    g_best[c][idx] = 0xFF800000u;   // enc(+inf); dir d queries live in cloud d
}

// ============================================================================
// 2) prefix-sum; zero hist/cursor; init slice-range accumulators. 1 blk, 2 warps.
// ============================================================================
__global__ void k_scan() {
    int lane = threadIdx.x & 31;
    int c    = threadIdx.x >> 5;
    int h[8], s8 = 0;
#pragma unroll
    for (int k = 0; k < 8; k++) { h[k] = g_hist[c][lane * 8 + k]; s8 += h[k]; }
    int incl = s8;
#pragma unroll
    for (int off = 1; off < 32; off <<= 1) {
        int v = __shfl_up_sync(0xffffffffu, incl, off);
        if (lane >= off) incl += v;
    }
    int run = incl - s8;
#pragma unroll
    for (int k = 0; k < 8; k++) { g_start[c][lane * 8 + k] = run; run += h[k]; }
    if (lane == 31) g_start[c][NBINS] = run;
#pragma unroll
    for (int k = 0; k < 8; k++) {
        g_hist[c][lane * 8 + k]   = 0;
        g_cursor[c][lane * 8 + k] = 0;
    }
    if (lane < NSLICE) { g_exlo[c][lane] = 0xFFFFFFFFu; g_exhi[c][lane] = 0u; }
}

// ============================================================================
// 3) counting-sort scatter: sorted points + fp16-split B fragments + exact
//    slice x-ranges via encoded REDG min/max.
// ============================================================================
__global__ void k_scatter(const float* __restrict__ adv, const float* __restrict__ ori) {
    int i = blockIdx.x * blockDim.x + threadIdx.x;
    int c = i >> 14, idx = i & (NPTS - 1);
    const float* src = c ? ori : adv;
    float x = src[3 * idx], y = src[3 * idx + 1], z = src[3 * idx + 2];
    int bin = min(max((int)((x - XLO) * (1.0f / XWIDTH)), 0), NBINS - 1);
    int pos = g_start[c][bin] + atomicAdd(&g_cursor[c][bin], 1);

    g_pts[c][pos] = make_float4(x, y, z, __int_as_float(idx));
    int s = pos >> 10;              // pos / SLICEN
    unsigned ex = enc_f(x);
    atomicMin(&g_exlo[c][s], ex);
    atomicMax(&g_exhi[c][s], ex);

    __half xh = __float2half_rn(x), yh = __float2half_rn(y), zh = __float2half_rn(z);
    __half xl = __float2half_rn(x - __half2float(xh));
    __half yl = __float2half_rn(y - __half2float(yh));
    __half zl = __float2half_rn(z - __half2float(zh));
    float tq = -0.5f * (x * x + y * y + z * z);
    __half tqh = __float2half_rn(tq);
    __half tql = __float2half_rn(tq - __half2float(tqh));
    __half hz  = __float2half_rn(0.f);
    unsigned Q0 = pkh2(xh, yh), Q1 = pkh2(zh, xh), Q2 = pkh2(yh, zh);
    unsigned Q3 = pkh2(xl, yl), Q4 = pkh2(zl, tqh), Q5 = pkh2(tql, hz);
    g_frag[c][pos][0] = make_uint4(Q0, Q4, Q1, Q5);
    g_frag[c][pos][1] = make_uint4(Q2, 0u, Q3, 0u);
}

// ---- stage query fragments into smem for in-warp exchange ----
static __device__ __forceinline__ void stage_query(
    int qc, int row, int tid, unsigned (*qA)[8], float* sQsq, float* sQx, int* sQid) {
    float4 p = g_pts[qc][row];
    float x = p.x, y = p.y, z = p.z;
    __half xh = __float2half_rn(x), yh = __float2half_rn(y), zh = __float2half_rn(z);
    __half xl = __float2half_rn(x - __half2float(xh));
    __half yl = __float2half_rn(y - __half2float(yh));
    __half zl = __float2half_rn(z - __half2float(zh));
    __half one = __float2half_rn(1.f), hz = __float2half_rn(0.f);
    qA[tid][0] = pkh2(xh, yh);  qA[tid][1] = pkh2(zh, one);
    qA[tid][2] = pkh2(zh, xl);  qA[tid][3] = pkh2(one, hz);
    qA[tid][4] = pkh2(yl, zl);  qA[tid][5] = 0u;
    qA[tid][6] = pkh2(xh, yh);  qA[tid][7] = 0u;
    sQsq[tid] = x * x + y * y + z * z;
    sQx[tid]  = x;
    sQid[tid] = __float_as_int(p.w);
}

// ============================================================================
// 4) seed: block = (dir, qt). Home-slice sweep (smem-staged, 8x reuse);
//    atomicMin per-row best + per-warp bound/x-range for the sweep phase.
// ============================================================================
__global__ void __launch_bounds__(TPB)
k_seed() {
    __shared__ uint4    sB4[SLICEN * 2];   // 32 KB
    __shared__ unsigned qA[QPB][8];
    __shared__ float    sQsq[QPB], sQx[QPB];
    __shared__ int      sQid[QPB];

    int b = blockIdx.x, dir = b / QT, qt = b % QT;
    int qc = dir, tc = 1 - dir;
    int tid = threadIdx.x;
    int home = qt >> 2, tb = home * SLICEN;

    stage_query(qc, qt * QPB + tid, tid, qA, sQsq, sQx, sQid);
    for (int k = tid; k < SLICEN * 2; k += TPB) sB4[k] = g_frag[tc][tb + (k >> 1)][k & 1];
    __syncthreads();

    int lane = tid & 31, warp = tid >> 5;
    int gid = lane >> 2, tl = lane & 3;
    int lr = warp * 32 + gid;

    uint2 u0 = *reinterpret_cast<const uint2*>(&qA[lr +  0][2 * tl]);
    uint2 u1 = *reinterpret_cast<const uint2*>(&qA[lr +  8][2 * tl]);
    uint2 u2 = *reinterpret_cast<const uint2*>(&qA[lr + 16][2 * tl]);
    uint2 u3 = *reinterpret_cast<const uint2*>(&qA[lr + 24][2 * tl]);
    unsigned a00 = u0.x, a01 = u1.x, a02 = u0.y, a03 = u1.y;
    unsigned a10 = u2.x, a11 = u3.x, a12 = u2.y, a13 = u3.y;

    float ninf = __int_as_float(0xFF800000);
    float mx00 = ninf, mx01 = ninf, mx10 = ninf, mx11 = ninf;
    const float zf = 0.0f;
    const uint2* sb = reinterpret_cast<const uint2*>(sB4);

#pragma unroll 4
    for (int j = 0; j < SLICEN; j += 8) {
        uint2 bb = sb[(j + gid) * 4 + tl];
        float d0, d1, d2, d3;
        MMA_F16(d0, d1, d2, d3, a00, a01, a02, a03, bb.x, bb.y, zf, zf, zf, zf);
        mx00 = fmaxf(mx00, fmaxf(d0, d1));
        mx01 = fmaxf(mx01, fmaxf(d2, d3));
        MMA_F16(d0, d1, d2, d3, a10, a11, a12, a13, bb.x, bb.y, zf, zf, zf, zf);
        mx10 = fmaxf(mx10, fmaxf(d0, d1));
        mx11 = fmaxf(mx11, fmaxf(d2, d3));
    }
#pragma unroll
    for (int off = 1; off <= 2; off <<= 1) {
        mx00 = fmaxf(mx00, __shfl_xor_sync(0xffffffffu, mx00, off));
        mx01 = fmaxf(mx01, __shfl_xor_sync(0xffffffffu, mx01, off));
        mx10 = fmaxf(mx10, __shfl_xor_sync(0xffffffffu, mx10, off));
        mx11 = fmaxf(mx11, __shfl_xor_sync(0xffffffffu, mx11, off));
    }
    float d0 = fmaf(-2.f, mx00, sQsq[lr +  0]);
    float d1 = fmaf(-2.f, mx01, sQsq[lr +  8]);
    float d2 = fmaf(-2.f, mx10, sQsq[lr + 16]);
    float d3 = fmaf(-2.f, mx11, sQsq[lr + 24]);
    if (tl == 0) {
        atomicMin(&g_best[dir][sQid[lr +  0]], enc_f(d0));
        atomicMin(&g_best[dir][sQid[lr +  8]], enc_f(d1));
        atomicMin(&g_best[dir][sQid[lr + 16]], enc_f(d2));
        atomicMin(&g_best[dir][sQid[lr + 24]], enc_f(d3));
    }
    float bnd = fmaxf(fmaxf(d0, d1), fmaxf(d2, d3));
    float xlo = fminf(fminf(sQx[lr], sQx[lr + 8]), fminf(sQx[lr + 16], sQx[lr + 24]));
    float xhi = fmaxf(fmaxf(sQx[lr], sQx[lr + 8]), fmaxf(sQx[lr + 16], sQx[lr + 24]));
#pragma unroll
    for (int off = 16; off >= 1; off >>= 1) {
        bnd = fmaxf(bnd, __shfl_xor_sync(0xffffffffu, bnd, off));
        xlo = fminf(xlo, __shfl_xor_sync(0xffffffffu, xlo, off));
        xhi = fmaxf(xhi, __shfl_xor_sync(0xffffffffu, xhi, off));
    }
    if (lane == 0) {
        g_wb [dir][qt][warp] = bnd;
        g_wlo[dir][qt][warp] = xlo;
        g_whi[dir][qt][warp] = xhi;
    }
}

// ============================================================================
// 5) sweep: block = (dir, qt, sp). Per-warp prune; survivors stream their
//    slice straight from L2 (no smem staging) and atomicMin per-row best.
// ============================================================================
__global__ void __launch_bounds__(TPB)
k_sweep() {
    __shared__ unsigned qA[QPB][8];
    __shared__ float    sQsq[QPB], sQx[QPB];
    __shared__ int      sQid[QPB];

    int b = blockIdx.x;
    int dir = b / (QT * NSLICE);
    int rem = b % (QT * NSLICE);
    int qt = rem / NSLICE, sp = rem % NSLICE;
    int qc = dir, tc = 1 - dir;
    int tid = threadIdx.x;
    int warp = tid >> 5, lane = tid & 31;
    int home = qt >> 2;

    int pruned;
    if (sp == home) {
        pruned = 1;
    } else {
        float wb  = g_wb [dir][qt][warp];
        float wlo = g_wlo[dir][qt][warp];
        float whi = g_whi[dir][qt][warp];
        float slo = dec_f(g_exlo[tc][sp]), shi = dec_f(g_exhi[tc][sp]);
        float gap = fmaxf(0.f, fmaxf(slo - whi, wlo - shi));
        pruned = (gap * gap > wb + 1e-3f);
    }
    if (__syncthreads_and(pruned)) return;

    stage_query(qc, qt * QPB + tid, tid, qA, sQsq, sQx, sQid);
    __syncthreads();
    if (pruned) return;

    int gid = lane >> 2, tl = lane & 3;
    int lr = warp * 32 + gid;
    uint2 u0 = *reinterpret_cast<const uint2*>(&qA[lr +  0][2 * tl]);
    uint2 u1 = *reinterpret_cast<const uint2*>(&qA[lr +  8][2 * tl]);
    uint2 u2 = *reinterpret_cast<const uint2*>(&qA[lr + 16][2 * tl]);
    uint2 u3 = *reinterpret_cast<const uint2*>(&qA[lr + 24][2 * tl]);
    unsigned a00 = u0.x, a01 = u1.x, a02 = u0.y, a03 = u1.y;
    unsigned a10 = u2.x, a11 = u3.x, a12 = u2.y, a13 = u3.y;

    float ninf = __int_as_float(0xFF800000);
    float mx00 = ninf, mx01 = ninf, mx10 = ninf, mx11 = ninf;
    const float zf = 0.0f;
    const uint2* fb = reinterpret_cast<const uint2*>(&g_frag[tc][0][0]);
    int tb = sp * SLICEN;

#pragma unroll 4
    for (int j = 0; j < SLICEN; j += 8) {
        uint2 bb = fb[(tb + j + gid) * 4 + tl];
        float d0, d1, d2, d3;
        MMA_F16(d0, d1, d2, d3, a00, a01, a02, a03, bb.x, bb.y, zf, zf, zf, zf);
        mx00 = fmaxf(mx00, fmaxf(d0, d1));
        mx01 = fmaxf(mx01, fmaxf(d2, d3));
        MMA_F16(d0, d1, d2, d3, a10, a11, a12, a13, bb.x, bb.y, zf, zf, zf, zf);
        mx10 = fmaxf(mx10, fmaxf(d0, d1));
        mx11 = fmaxf(mx11, fmaxf(d2, d3));
    }
#pragma unroll
    for (int off = 1; off <= 2; off <<= 1) {
        mx00 = fmaxf(mx00, __shfl_xor_sync(0xffffffffu, mx00, off));
        mx01 = fmaxf(mx01, __shfl_xor_sync(0xffffffffu, mx01, off));
        mx10 = fmaxf(mx10, __shfl_xor_sync(0xffffffffu, mx10, off));
        mx11 = fmaxf(mx11, __shfl_xor_sync(0xffffffffu, mx11, off));
    }
    if (tl == 0) {
        atomicMin(&g_best[dir][sQid[lr +  0]], enc_f(fmaf(-2.f, mx00, sQsq[lr +  0])));
        atomicMin(&g_best[dir][sQid[lr +  8]], enc_f(fmaf(-2.f, mx01, sQsq[lr +  8])));
        atomicMin(&g_best[dir][sQid[lr + 16]], enc_f(fmaf(-2.f, mx10, sQsq[lr + 16])));
        atomicMin(&g_best[dir][sQid[lr + 24]], enc_f(fmaf(-2.f, mx11, sQsq[lr + 24])));
    }
}

// ============================================================================
// 6) fused reduction: block partial sums + last-block-ticket final sum
//    (final block adds the 128 partials in fixed order -> deterministic).
// ============================================================================
__global__ void __launch_bounds__(TPB)
k_red(float* __restrict__ out) {
    __shared__ float sh[TPB];
    __shared__ int   amLast;
    int rid = blockIdx.x * TPB + threadIdx.x;
    int dir = rid >> 14, row = rid & (NPTS - 1);
    sh[threadIdx.x] = dec_f(g_best[dir][row]);
    __syncthreads();
    for (int k = TPB / 2; k > 0; k >>= 1) {
        if (threadIdx.x < k) sh[threadIdx.x] += sh[threadIdx.x + k];
        __syncthreads();
    }
    if (threadIdx.x == 0) {
        g_bsum[blockIdx.x] = sh[0];
        __threadfence();
        amLast = (atomicAdd(&g_ticket, 1u) == REDB - 1);
    }
    __syncthreads();
    if (amLast && threadIdx.x == 0) {
        float s = 0.f;
#pragma unroll
        for (int k = 0; k < REDB; k++) s += g_bsum[k];
        out[0] = s / (float)NPTS;
        g_ticket = 0;   // reset for next graph replay
    }
}

extern "C" void kernel_launch(void* const* d_in, const int* in_sizes, int n_in,
                              void* d_out, int out_size) {
    const float* adv = (const float*)d_in[0];
    const float* ori = (const float*)d_in[1];
    k_hist<<<2 * NPTS / 256, 256>>>(adv, ori);
    k_scan<<<1, 64>>>();
    k_scatter<<<2 * NPTS / 256, 256>>>(adv, ori);
    k_seed<<<2 * QT, TPB>>>();
    k_sweep<<<2 * QT * NSLICE, TPB>>>();
    k_red<<<REDB, TPB>>>((float*)d_out);
}

// round 8
// speedup vs baseline: 1.0579x; 1.0579x over previous
#include <cuda_runtime.h>
#include <cuda_fp16.h>
#include <cstdint>

#define NPTS    16384
#define NBINS   256
#define NSLICE  16
#define SLICEN  (NPTS/NSLICE)      // 1024 targets per slice
#define SQUART  4                  // seed quarters per home slice
#define SEEDN   (SLICEN/SQUART)    // 256 targets per seed block
#define TPB     256
#define QPB     256                // queries per tile
#define QT      (NPTS/QPB)         // 64 tiles per direction
#define WPB     8
#define REDB    (2*NPTS/TPB)       // 128 reduction blocks
#define XLO     (-8.0f)
#define XWIDTH  (16.0f/NBINS)

// ---- pipeline state; everything transient is re-initialized each replay ----
__device__ int      g_hist[2][NBINS];
__device__ int      g_start[2][NBINS + 1];
__device__ int      g_cursor[2][NBINS];
__device__ unsigned g_exlo[2][NSLICE], g_exhi[2][NSLICE]; // encoded slice x-ranges
__device__ float4   g_pts[2][NPTS];          // sorted (x,y,z, orig_idx bits)
__device__ uint4    g_frag[2][NPTS][2];      // target B-fragments, sorted order
__device__ unsigned g_best[2][NPTS];         // per-row best dist (encoded), atomicMin
__device__ unsigned g_wb[2][QT][WPB];        // per-warp seed bound (encoded, atomicMin)
__device__ float    g_wlo[2][QT][WPB], g_whi[2][QT][WPB];
__device__ float    g_bsum[REDB];
__device__ unsigned g_ticket;

// ---- order-preserving float<->uint encode ----
static __device__ __forceinline__ unsigned enc_f(float f) {
    unsigned u = __float_as_uint(f);
    return (u & 0x80000000u) ? ~u : (u | 0x80000000u);
}
static __device__ __forceinline__ float dec_f(unsigned u) {
    unsigned b = (u & 0x80000000u) ? (u & 0x7fffffffu) : ~u;
    return __uint_as_float(b);
}
static __device__ __forceinline__ unsigned pkh2(__half lo, __half hi) {
    __half2 h = __halves2half2(lo, hi);
    return *reinterpret_cast<unsigned*>(&h);
}

// m16n8k16 fp16 MMA, fp32 accumulate. A row-major, B col-major.
#define MMA_F16(d0,d1,d2,d3, a0,a1,a2,a3, b0,b1, c0,c1,c2,c3)                       \
    asm("mma.sync.aligned.m16n8k16.row.col.f32.f16.f16.f32 "                        \
        "{%0,%1,%2,%3}, {%4,%5,%6,%7}, {%8,%9}, {%10,%11,%12,%13};"                 \
        : "=f"(d0), "=f"(d1), "=f"(d2), "=f"(d3)                                    \
        : "r"(a0), "r"(a1), "r"(a2), "r"(a3), "r"(b0), "r"(b1),                     \
          "f"(c0), "f"(c1), "f"(c2), "f"(c3))

// ============================================================================
// 1) x-histogram + per-row best init (each (dir,row) touched exactly once)
// ============================================================================
__global__ void k_hist(const float* __restrict__ adv, const float* __restrict__ ori) {
    int i = blockIdx.x * blockDim.x + threadIdx.x;
    int c = i >> 14, idx = i & (NPTS - 1);
    const float* src = c ? ori : adv;
    float x = src[3 * idx];
    int bin = min(max((int)((x - XLO) * (1.0f / XWIDTH)), 0), NBINS - 1);
    atomicAdd(&g_hist[c][bin], 1);
    g_best[c][idx] = 0xFF800000u;   // enc(+inf)
}

// ============================================================================
// 2) prefix-sum; zero hist/cursor; init slice-range + warp-bound accumulators.
// ============================================================================
__global__ void k_scan() {
    int lane = threadIdx.x & 31;
    int c    = threadIdx.x >> 5;
    int h[8], s8 = 0;
#pragma unroll
    for (int k = 0; k < 8; k++) { h[k] = g_hist[c][lane * 8 + k]; s8 += h[k]; }
    int incl = s8;
#pragma unroll
    for (int off = 1; off < 32; off <<= 1) {
        int v = __shfl_up_sync(0xffffffffu, incl, off);
        if (lane >= off) incl += v;
    }
    int run = incl - s8;
#pragma unroll
    for (int k = 0; k < 8; k++) { g_start[c][lane * 8 + k] = run; run += h[k]; }
    if (lane == 31) g_start[c][NBINS] = run;
#pragma unroll
    for (int k = 0; k < 8; k++) {
        g_hist[c][lane * 8 + k]   = 0;
        g_cursor[c][lane * 8 + k] = 0;
    }
    if (lane < NSLICE) { g_exlo[c][lane] = 0xFFFFFFFFu; g_exhi[c][lane] = 0u; }
    // init per-warp bounds: QT*WPB = 512 entries per dir, 16 per lane
    unsigned* wb = &g_wb[c][0][0];
#pragma unroll
    for (int k = 0; k < QT * WPB / 32; k++) wb[lane + k * 32] = 0xFF800000u;
}

// ============================================================================
// 3) counting-sort scatter: sorted points + fp16-split B fragments + exact
//    slice x-ranges via encoded min/max atomics.
// ============================================================================
__global__ void k_scatter(const float* __restrict__ adv, const float* __restrict__ ori) {
    int i = blockIdx.x * blockDim.x + threadIdx.x;
    int c = i >> 14, idx = i & (NPTS - 1);
    const float* src = c ? ori : adv;
    float x = src[3 * idx], y = src[3 * idx + 1], z = src[3 * idx + 2];
    int bin = min(max((int)((x - XLO) * (1.0f / XWIDTH)), 0), NBINS - 1);
    int pos = g_start[c][bin] + atomicAdd(&g_cursor[c][bin], 1);

    g_pts[c][pos] = make_float4(x, y, z, __int_as_float(idx));
    int s = pos >> 10;              // pos / SLICEN
    unsigned ex = enc_f(x);
    atomicMin(&g_exlo[c][s], ex);
    atomicMax(&g_exhi[c][s], ex);

    __half xh = __float2half_rn(x), yh = __float2half_rn(y), zh = __float2half_rn(z);
    __half xl = __float2half_rn(x - __half2float(xh));
    __half yl = __float2half_rn(y - __half2float(yh));
    __half zl = __float2half_rn(z - __half2float(zh));
    float tq = -0.5f * (x * x + y * y + z * z);
    __half tqh = __float2half_rn(tq);
    __half tql = __float2half_rn(tq - __half2float(tqh));
    __half hz  = __float2half_rn(0.f);
    unsigned Q0 = pkh2(xh, yh), Q1 = pkh2(zh, xh), Q2 = pkh2(yh, zh);
    unsigned Q3 = pkh2(xl, yl), Q4 = pkh2(zl, tqh), Q5 = pkh2(tql, hz);
    g_frag[c][pos][0] = make_uint4(Q0, Q4, Q1, Q5);
    g_frag[c][pos][1] = make_uint4(Q2, 0u, Q3, 0u);
}

// ---- stage query fragments into smem for in-warp exchange ----
static __device__ __forceinline__ void stage_query(
    int qc, int row, int tid, unsigned (*qA)[8], float* sQsq, float* sQx, int* sQid) {
    float4 p = g_pts[qc][row];
    float x = p.x, y = p.y, z = p.z;
    __half xh = __float2half_rn(x), yh = __float2half_rn(y), zh = __float2half_rn(z);
    __half xl = __float2half_rn(x - __half2float(xh));
    __half yl = __float2half_rn(y - __half2float(yh));
    __half zl = __float2half_rn(z - __half2float(zh));
    __half one = __float2half_rn(1.f), hz = __float2half_rn(0.f);
    qA[tid][0] = pkh2(xh, yh);  qA[tid][1] = pkh2(zh, one);
    qA[tid][2] = pkh2(zh, xl);  qA[tid][3] = pkh2(one, hz);
    qA[tid][4] = pkh2(yl, zl);  qA[tid][5] = 0u;
    qA[tid][6] = pkh2(xh, yh);  qA[tid][7] = 0u;
    sQsq[tid] = x * x + y * y + z * z;
    sQx[tid]  = x;
    sQid[tid] = __float_as_int(p.w);
}

// ============================================================================
// 4) seed: block = (dir, qt, quarter). Sweeps 256 home targets; atomicMin
//    per-row best + encoded-atomicMin per-warp bound. Grid 512 -> good occ.
// ============================================================================
__global__ void __launch_bounds__(TPB)
k_seed() {
    __shared__ uint4    sB4[SEEDN * 2];    // 8 KB
    __shared__ unsigned qA[QPB][8];        // 8 KB
    __shared__ float    sQsq[QPB], sQx[QPB];
    __shared__ int      sQid[QPB];

    int b = blockIdx.x;
    int dir = b / (QT * SQUART);
    int rem = b % (QT * SQUART);
    int qt = rem / SQUART, qu = rem % SQUART;
    int qc = dir, tc = 1 - dir;
    int tid = threadIdx.x;
    int tb = (qt >> 2) * SLICEN + qu * SEEDN;

    stage_query(qc, qt * QPB + tid, tid, qA, sQsq, sQx, sQid);
    for (int k = tid; k < SEEDN * 2; k += TPB) sB4[k] = g_frag[tc][tb + (k >> 1)][k & 1];
    __syncthreads();

    int lane = tid & 31, warp = tid >> 5;
    int gid = lane >> 2, tl = lane & 3;
    int lr = warp * 32 + gid;

    uint2 u0 = *reinterpret_cast<const uint2*>(&qA[lr +  0][2 * tl]);
    uint2 u1 = *reinterpret_cast<const uint2*>(&qA[lr +  8][2 * tl]);
    uint2 u2 = *reinterpret_cast<const uint2*>(&qA[lr + 16][2 * tl]);
    uint2 u3 = *reinterpret_cast<const uint2*>(&qA[lr + 24][2 * tl]);
    unsigned a00 = u0.x, a01 = u1.x, a02 = u0.y, a03 = u1.y;
    unsigned a10 = u2.x, a11 = u3.x, a12 = u2.y, a13 = u3.y;

    float ninf = __int_as_float(0xFF800000);
    float mx00 = ninf, mx01 = ninf, mx10 = ninf, mx11 = ninf;
    const float zf = 0.0f;
    const uint2* sb = reinterpret_cast<const uint2*>(sB4);

#pragma unroll 4
    for (int j = 0; j < SEEDN; j += 8) {
        uint2 bb = sb[(j + gid) * 4 + tl];
        float d0, d1, d2, d3;
        MMA_F16(d0, d1, d2, d3, a00, a01, a02, a03, bb.x, bb.y, zf, zf, zf, zf);
        mx00 = fmaxf(mx00, fmaxf(d0, d1));
        mx01 = fmaxf(mx01, fmaxf(d2, d3));
        MMA_F16(d0, d1, d2, d3, a10, a11, a12, a13, bb.x, bb.y, zf, zf, zf, zf);
        mx10 = fmaxf(mx10, fmaxf(d0, d1));
        mx11 = fmaxf(mx11, fmaxf(d2, d3));
    }
#pragma unroll
    for (int off = 1; off <= 2; off <<= 1) {
        mx00 = fmaxf(mx00, __shfl_xor_sync(0xffffffffu, mx00, off));
        mx01 = fmaxf(mx01, __shfl_xor_sync(0xffffffffu, mx01, off));
        mx10 = fmaxf(mx10, __shfl_xor_sync(0xffffffffu, mx10, off));
        mx11 = fmaxf(mx11, __shfl_xor_sync(0xffffffffu, mx11, off));
    }
    float d0 = fmaf(-2.f, mx00, sQsq[lr +  0]);
    float d1 = fmaf(-2.f, mx01, sQsq[lr +  8]);
    float d2 = fmaf(-2.f, mx10, sQsq[lr + 16]);
    float d3 = fmaf(-2.f, mx11, sQsq[lr + 24]);
    if (tl == 0) {
        atomicMin(&g_best[dir][sQid[lr +  0]], enc_f(d0));
        atomicMin(&g_best[dir][sQid[lr +  8]], enc_f(d1));
        atomicMin(&g_best[dir][sQid[lr + 16]], enc_f(d2));
        atomicMin(&g_best[dir][sQid[lr + 24]], enc_f(d3));
    }
    // per-warp bound (quarter-local, merged across quarters via atomicMin)
    float bnd = fmaxf(fmaxf(d0, d1), fmaxf(d2, d3));
    float xlo = fminf(fminf(sQx[lr], sQx[lr + 8]), fminf(sQx[lr + 16], sQx[lr + 24]));
    float xhi = fmaxf(fmaxf(sQx[lr], sQx[lr + 8]), fmaxf(sQx[lr + 16], sQx[lr + 24]));
#pragma unroll
    for (int off = 16; off >= 1; off >>= 1) {
        bnd = fmaxf(bnd, __shfl_xor_sync(0xffffffffu, bnd, off));
        xlo = fminf(xlo, __shfl_xor_sync(0xffffffffu, xlo, off));
        xhi = fmaxf(xhi, __shfl_xor_sync(0xffffffffu, xhi, off));
    }
    if (lane == 0) {
        atomicMin(&g_wb[dir][qt][warp], enc_f(bnd));
        g_wlo[dir][qt][warp] = xlo;   // identical across quarters
        g_whi[dir][qt][warp] = xhi;
    }
}

// ============================================================================
// 5) sweep: block = (dir, qt, sp). Per-warp prune; all threads (incl. pruned
//    warps) cooperatively stage the 32KB B tile, then pruned warps exit.
// ============================================================================
__global__ void __launch_bounds__(TPB)
k_sweep() {
    __shared__ uint4    sB4[SLICEN * 2];   // 32 KB
    __shared__ unsigned qA[QPB][8];
    __shared__ float    sQsq[QPB], sQx[QPB];
    __shared__ int      sQid[QPB];

    int b = blockIdx.x;
    int dir = b / (QT * NSLICE);
    int rem = b % (QT * NSLICE);
    int qt = rem / NSLICE, sp = rem % NSLICE;
    int qc = dir, tc = 1 - dir;
    int tid = threadIdx.x;
    int warp = tid >> 5, lane = tid & 31;
    int home = qt >> 2;

    int pruned;
    if (sp == home) {
        pruned = 1;   // covered by seed
    } else {
        float wb  = dec_f(g_wb[dir][qt][warp]);
        float wlo = g_wlo[dir][qt][warp];
        float whi = g_whi[dir][qt][warp];
        float slo = dec_f(g_exlo[tc][sp]), shi = dec_f(g_exhi[tc][sp]);
        float gap = fmaxf(0.f, fmaxf(slo - whi, wlo - shi));
        pruned = (gap * gap > wb + 1e-3f);
    }
    if (__syncthreads_and(pruned)) return;

    stage_query(qc, qt * QPB + tid, tid, qA, sQsq, sQx, sQid);
    {
        int tb = sp * SLICEN;
        for (int k = tid; k < SLICEN * 2; k += TPB) sB4[k] = g_frag[tc][tb + (k >> 1)][k & 1];
    }
    __syncthreads();
    if (pruned) return;

    int gid = lane >> 2, tl = lane & 3;
    int lr = warp * 32 + gid;
    uint2 u0 = *reinterpret_cast<const uint2*>(&qA[lr +  0][2 * tl]);
    uint2 u1 = *reinterpret_cast<const uint2*>(&qA[lr +  8][2 * tl]);
    uint2 u2 = *reinterpret_cast<const uint2*>(&qA[lr + 16][2 * tl]);
    uint2 u3 = *reinterpret_cast<const uint2*>(&qA[lr + 24][2 * tl]);
    unsigned a00 = u0.x, a01 = u1.x, a02 = u0.y, a03 = u1.y;
    unsigned a10 = u2.x, a11 = u3.x, a12 = u2.y, a13 = u3.y;

    float ninf = __int_as_float(0xFF800000);
    float mx00 = ninf, mx01 = ninf, mx10 = ninf, mx11 = ninf;
    const float zf = 0.0f;
    const uint2* sb = reinterpret_cast<const uint2*>(sB4);

#pragma unroll 4
    for (int j = 0; j < SLICEN; j += 8) {
        uint2 bb = sb[(j + gid) * 4 + tl];
        float d0, d1, d2, d3;
        MMA_F16(d0, d1, d2, d3, a00, a01, a02, a03, bb.x, bb.y, zf, zf, zf, zf);
        mx00 = fmaxf(mx00, fmaxf(d0, d1));
        mx01 = fmaxf(mx01, fmaxf(d2, d3));
        MMA_F16(d0, d1, d2, d3, a10, a11, a12, a13, bb.x, bb.y, zf, zf, zf, zf);
        mx10 = fmaxf(mx10, fmaxf(d0, d1));
        mx11 = fmaxf(mx11, fmaxf(d2, d3));
    }
#pragma unroll
    for (int off = 1; off <= 2; off <<= 1) {
        mx00 = fmaxf(mx00, __shfl_xor_sync(0xffffffffu, mx00, off));
        mx01 = fmaxf(mx01, __shfl_xor_sync(0xffffffffu, mx01, off));
        mx10 = fmaxf(mx10, __shfl_xor_sync(0xffffffffu, mx10, off));
        mx11 = fmaxf(mx11, __shfl_xor_sync(0xffffffffu, mx11, off));
    }
    if (tl == 0) {
        atomicMin(&g_best[dir][sQid[lr +  0]], enc_f(fmaf(-2.f, mx00, sQsq[lr +  0])));
        atomicMin(&g_best[dir][sQid[lr +  8]], enc_f(fmaf(-2.f, mx01, sQsq[lr +  8])));
        atomicMin(&g_best[dir][sQid[lr + 16]], enc_f(fmaf(-2.f, mx10, sQsq[lr + 16])));
        atomicMin(&g_best[dir][sQid[lr + 24]], enc_f(fmaf(-2.f, mx11, sQsq[lr + 24])));
    }
}

// ============================================================================
// 6) fused reduction: block partial sums + last-block-ticket final sum.
// ============================================================================
__global__ void __launch_bounds__(TPB)
k_red(float* __restrict__ out) {
    __shared__ float sh[TPB];
    __shared__ int   amLast;
    int rid = blockIdx.x * TPB + threadIdx.x;
    int dir = rid >> 14, row = rid & (NPTS - 1);
    sh[threadIdx.x] = dec_f(g_best[dir][row]);
    __syncthreads();
    for (int k = TPB / 2; k > 0; k >>= 1) {
        if (threadIdx.x < k) sh[threadIdx.x] += sh[threadIdx.x + k];
        __syncthreads();
    }
    if (threadIdx.x == 0) {
        g_bsum[blockIdx.x] = sh[0];
        __threadfence();
        amLast = (atomicAdd(&g_ticket, 1u) == REDB - 1);
    }
    __syncthreads();
    if (amLast && threadIdx.x == 0) {
        float s = 0.f;
#pragma unroll
        for (int k = 0; k < REDB; k++) s += g_bsum[k];
        out[0] = s / (float)NPTS;
        g_ticket = 0;   // reset for next graph replay
    }
}

extern "C" void kernel_launch(void* const* d_in, const int* in_sizes, int n_in,
                              void* d_out, int out_size) {
    const float* adv = (const float*)d_in[0];
    const float* ori = (const float*)d_in[1];
    k_hist<<<2 * NPTS / 256, 256>>>(adv, ori);
    k_scan<<<1, 64>>>();
    k_scatter<<<2 * NPTS / 256, 256>>>(adv, ori);
    k_seed<<<2 * QT * SQUART, TPB>>>();
    k_sweep<<<2 * QT * NSLICE, TPB>>>();
    k_red<<<REDB, TPB>>>((float*)d_out);
}

// round 9
// speedup vs baseline: 1.0586x; 1.0007x over previous
#include <cuda_runtime.h>
#include <cuda_fp16.h>
#include <cstdint>

#define NPTS    16384
#define NBINS   256
#define NSLICE  16
#define SLICEN  (NPTS/NSLICE)      // 1024 targets per slice
#define SQUART  4                  // seed quarters per home slice
#define SEEDN   (SLICEN/SQUART)    // 256 targets per seed block
#define TPB     256
#define QPB     256                // queries per tile
#define QT      (NPTS/QPB)         // 64 tiles per direction
#define REDB    (2*NPTS/TPB)       // 128 reduction blocks
#define XLO     (-8.0f)
#define XWIDTH  (16.0f/NBINS)

// ---- pipeline state; everything transient is re-initialized each replay ----
__device__ int      g_hist[2][NBINS];
__device__ int      g_start[2][NBINS + 1];
__device__ int      g_cursor[2][NBINS];
__device__ unsigned g_exlo[2][NSLICE], g_exhi[2][NSLICE]; // encoded slice x-ranges
__device__ float4   g_pts[2][NPTS];          // sorted (x,y,z, orig_idx bits)
__device__ uint4    g_frag[2][NPTS][2];      // target B-fragments, sorted order
__device__ unsigned g_best[2][NPTS];         // per-row best dist (encoded), atomicMin
__device__ float    g_bsum[REDB];
__device__ unsigned g_ticket;

// ---- order-preserving float<->uint encode ----
static __device__ __forceinline__ unsigned enc_f(float f) {
    unsigned u = __float_as_uint(f);
    return (u & 0x80000000u) ? ~u : (u | 0x80000000u);
}
static __device__ __forceinline__ float dec_f(unsigned u) {
    unsigned b = (u & 0x80000000u) ? (u & 0x7fffffffu) : ~u;
    return __uint_as_float(b);
}
static __device__ __forceinline__ unsigned pkh2(__half lo, __half hi) {
    __half2 h = __halves2half2(lo, hi);
    return *reinterpret_cast<unsigned*>(&h);
}

// m16n8k16 fp16 MMA, fp32 accumulate. A row-major, B col-major.
#define MMA_F16(d0,d1,d2,d3, a0,a1,a2,a3, b0,b1, c0,c1,c2,c3)                       \
    asm("mma.sync.aligned.m16n8k16.row.col.f32.f16.f16.f32 "                        \
        "{%0,%1,%2,%3}, {%4,%5,%6,%7}, {%8,%9}, {%10,%11,%12,%13};"                 \
        : "=f"(d0), "=f"(d1), "=f"(d2), "=f"(d3)                                    \
        : "r"(a0), "r"(a1), "r"(a2), "r"(a3), "r"(b0), "r"(b1),                     \
          "f"(c0), "f"(c1), "f"(c2), "f"(c3))

// ============================================================================
// 1) x-histogram + per-row best init (each (dir,row) touched exactly once)
// ============================================================================
__global__ void k_hist(const float* __restrict__ adv, const float* __restrict__ ori) {
    int i = blockIdx.x * blockDim.x + threadIdx.x;
    int c = i >> 14, idx = i & (NPTS - 1);
    const float* src = c ? ori : adv;
    float x = src[3 * idx];
    int bin = min(max((int)((x - XLO) * (1.0f / XWIDTH)), 0), NBINS - 1);
    atomicAdd(&g_hist[c][bin], 1);
    g_best[c][idx] = 0xFF800000u;   // enc(+inf)
}

// ============================================================================
// 2) prefix-sum; zero hist/cursor; init slice-range accumulators. 1 blk, 2 warps.
// ============================================================================
__global__ void k_scan() {
    int lane = threadIdx.x & 31;
    int c    = threadIdx.x >> 5;
    int h[8], s8 = 0;
#pragma unroll
    for (int k = 0; k < 8; k++) { h[k] = g_hist[c][lane * 8 + k]; s8 += h[k]; }
    int incl = s8;
#pragma unroll
    for (int off = 1; off < 32; off <<= 1) {
        int v = __shfl_up_sync(0xffffffffu, incl, off);
        if (lane >= off) incl += v;
    }
    int run = incl - s8;
#pragma unroll
    for (int k = 0; k < 8; k++) { g_start[c][lane * 8 + k] = run; run += h[k]; }
    if (lane == 31) g_start[c][NBINS] = run;
#pragma unroll
    for (int k = 0; k < 8; k++) {
        g_hist[c][lane * 8 + k]   = 0;
        g_cursor[c][lane * 8 + k] = 0;
    }
    if (lane < NSLICE) { g_exlo[c][lane] = 0xFFFFFFFFu; g_exhi[c][lane] = 0u; }
}

// ============================================================================
// 3) counting-sort scatter: sorted points + fp16-split B fragments + exact
//    slice x-ranges via encoded min/max atomics.
// ============================================================================
__global__ void k_scatter(const float* __restrict__ adv, const float* __restrict__ ori) {
    int i = blockIdx.x * blockDim.x + threadIdx.x;
    int c = i >> 14, idx = i & (NPTS - 1);
    const float* src = c ? ori : adv;
    float x = src[3 * idx], y = src[3 * idx + 1], z = src[3 * idx + 2];
    int bin = min(max((int)((x - XLO) * (1.0f / XWIDTH)), 0), NBINS - 1);
    int pos = g_start[c][bin] + atomicAdd(&g_cursor[c][bin], 1);

    g_pts[c][pos] = make_float4(x, y, z, __int_as_float(idx));
    int s = pos >> 10;              // pos / SLICEN
    unsigned ex = enc_f(x);
    atomicMin(&g_exlo[c][s], ex);
    atomicMax(&g_exhi[c][s], ex);

    __half xh = __float2half_rn(x), yh = __float2half_rn(y), zh = __float2half_rn(z);
    __half xl = __float2half_rn(x - __half2float(xh));
    __half yl = __float2half_rn(y - __half2float(yh));
    __half zl = __float2half_rn(z - __half2float(zh));
    float tq = -0.5f * (x * x + y * y + z * z);
    __half tqh = __float2half_rn(tq);
    __half tql = __float2half_rn(tq - __half2float(tqh));
    __half hz  = __float2half_rn(0.f);
    unsigned Q0 = pkh2(xh, yh), Q1 = pkh2(zh, xh), Q2 = pkh2(yh, zh);
    unsigned Q3 = pkh2(xl, yl), Q4 = pkh2(zl, tqh), Q5 = pkh2(tql, hz);
    g_frag[c][pos][0] = make_uint4(Q0, Q4, Q1, Q5);
    g_frag[c][pos][1] = make_uint4(Q2, 0u, Q3, 0u);
}

// ---- stage one query's fragments into smem (point already loaded) ----
static __device__ __forceinline__ void stage_query_p(
    float4 p, int tid, unsigned (*qA)[8], float* sQsq, int* sQid) {
    float x = p.x, y = p.y, z = p.z;
    __half xh = __float2half_rn(x), yh = __float2half_rn(y), zh = __float2half_rn(z);
    __half xl = __float2half_rn(x - __half2float(xh));
    __half yl = __float2half_rn(y - __half2float(yh));
    __half zl = __float2half_rn(z - __half2float(zh));
    __half one = __float2half_rn(1.f), hz = __float2half_rn(0.f);
    qA[tid][0] = pkh2(xh, yh);  qA[tid][1] = pkh2(zh, one);
    qA[tid][2] = pkh2(zh, xl);  qA[tid][3] = pkh2(one, hz);
    qA[tid][4] = pkh2(yl, zl);  qA[tid][5] = 0u;
    qA[tid][6] = pkh2(xh, yh);  qA[tid][7] = 0u;
    sQsq[tid] = x * x + y * y + z * z;
    sQid[tid] = __float_as_int(p.w);
}

// ---- the shared MMA inner sweep over TN targets from smem ----
static __device__ __forceinline__ void mma_sweep(
    const uint2* sb, int TN, unsigned a00, unsigned a01, unsigned a02, unsigned a03,
    unsigned a10, unsigned a11, unsigned a12, unsigned a13, int gid, int tl,
    float& mx00, float& mx01, float& mx10, float& mx11) {
    const float zf = 0.0f;
#pragma unroll 4
    for (int j = 0; j < TN; j += 8) {
        uint2 bb = sb[(j + gid) * 4 + tl];
        float d0, d1, d2, d3;
        MMA_F16(d0, d1, d2, d3, a00, a01, a02, a03, bb.x, bb.y, zf, zf, zf, zf);
        mx00 = fmaxf(mx00, fmaxf(d0, d1));
        mx01 = fmaxf(mx01, fmaxf(d2, d3));
        MMA_F16(d0, d1, d2, d3, a10, a11, a12, a13, bb.x, bb.y, zf, zf, zf, zf);
        mx10 = fmaxf(mx10, fmaxf(d0, d1));
        mx11 = fmaxf(mx11, fmaxf(d2, d3));
    }
}

// ============================================================================
// 4) seed: block = (dir, qt, quarter). Sweeps 256 home targets; atomicMin
//    per-row best. Bounds are NOT computed here (sweep derives them from
//    g_best, which is tight per query).
// ============================================================================
__global__ void __launch_bounds__(TPB)
k_seed() {
    __shared__ uint4    sB4[SEEDN * 2];    // 8 KB
    __shared__ unsigned qA[QPB][8];        // 8 KB
    __shared__ float    sQsq[QPB];
    __shared__ int      sQid[QPB];

    int b = blockIdx.x;
    int dir = b / (QT * SQUART);
    int rem = b % (QT * SQUART);
    int qt = rem / SQUART, qu = rem % SQUART;
    int qc = dir, tc = 1 - dir;
    int tid = threadIdx.x;
    int tb = (qt >> 2) * SLICEN + qu * SEEDN;

    stage_query_p(g_pts[qc][qt * QPB + tid], tid, qA, sQsq, sQid);
    for (int k = tid; k < SEEDN * 2; k += TPB) sB4[k] = g_frag[tc][tb + (k >> 1)][k & 1];
    __syncthreads();

    int lane = tid & 31, warp = tid >> 5;
    int gid = lane >> 2, tl = lane & 3;
    int lr = warp * 32 + gid;

    uint2 u0 = *reinterpret_cast<const uint2*>(&qA[lr +  0][2 * tl]);
    uint2 u1 = *reinterpret_cast<const uint2*>(&qA[lr +  8][2 * tl]);
    uint2 u2 = *reinterpret_cast<const uint2*>(&qA[lr + 16][2 * tl]);
    uint2 u3 = *reinterpret_cast<const uint2*>(&qA[lr + 24][2 * tl]);

    float ninf = __int_as_float(0xFF800000);
    float mx00 = ninf, mx01 = ninf, mx10 = ninf, mx11 = ninf;
    mma_sweep(reinterpret_cast<const uint2*>(sB4), SEEDN,
              u0.x, u1.x, u0.y, u1.y, u2.x, u3.x, u2.y, u3.y, gid, tl,
              mx00, mx01, mx10, mx11);

#pragma unroll
    for (int off = 1; off <= 2; off <<= 1) {
        mx00 = fmaxf(mx00, __shfl_xor_sync(0xffffffffu, mx00, off));
        mx01 = fmaxf(mx01, __shfl_xor_sync(0xffffffffu, mx01, off));
        mx10 = fmaxf(mx10, __shfl_xor_sync(0xffffffffu, mx10, off));
        mx11 = fmaxf(mx11, __shfl_xor_sync(0xffffffffu, mx11, off));
    }
    if (tl == 0) {
        atomicMin(&g_best[dir][sQid[lr +  0]], enc_f(fmaf(-2.f, mx00, sQsq[lr +  0])));
        atomicMin(&g_best[dir][sQid[lr +  8]], enc_f(fmaf(-2.f, mx01, sQsq[lr +  8])));
        atomicMin(&g_best[dir][sQid[lr + 16]], enc_f(fmaf(-2.f, mx10, sQsq[lr + 16])));
        atomicMin(&g_best[dir][sQid[lr + 24]], enc_f(fmaf(-2.f, mx11, sQsq[lr + 24])));
    }
}

// ============================================================================
// 5) sweep: block = (dir, qt, sp). Per-warp TIGHT bound computed in the
//    prologue from g_best (exact per-query home best); prune via x-gap.
//    Survivors cooperatively stage the 32KB B tile (pruned warps help).
// ============================================================================
__global__ void __launch_bounds__(TPB)
k_sweep() {
    __shared__ uint4    sB4[SLICEN * 2];   // 32 KB
    __shared__ unsigned qA[QPB][8];
    __shared__ float    sQsq[QPB];
    __shared__ int      sQid[QPB];

    int b = blockIdx.x;
    int dir = b / (QT * NSLICE);
    int rem = b % (QT * NSLICE);
    int qt = rem / NSLICE, sp = rem % NSLICE;
    int qc = dir, tc = 1 - dir;
    int tid = threadIdx.x;
    int warp = tid >> 5, lane = tid & 31;
    int home = qt >> 2;

    // ---- prologue: load own query point + its current best; warp bound ----
    float4 p = g_pts[qc][qt * QPB + tid];
    int pruned;
    if (sp == home) {
        pruned = 1;   // covered by seed
    } else {
        float bnd = dec_f(g_best[dir][__float_as_int(p.w)]);
        float wlo = p.x, whi = p.x;
#pragma unroll
        for (int off = 16; off >= 1; off >>= 1) {
            bnd = fmaxf(bnd, __shfl_xor_sync(0xffffffffu, bnd, off));
            wlo = fminf(wlo, __shfl_xor_sync(0xffffffffu, wlo, off));
            whi = fmaxf(whi, __shfl_xor_sync(0xffffffffu, whi, off));
        }
        float slo = dec_f(g_exlo[tc][sp]), shi = dec_f(g_exhi[tc][sp]);
        float gap = fmaxf(0.f, fmaxf(slo - whi, wlo - shi));
        pruned = (gap * gap > bnd + 1e-3f);
    }
    if (__syncthreads_and(pruned)) return;

    stage_query_p(p, tid, qA, sQsq, sQid);
    {
        int tb = sp * SLICEN;
        for (int k = tid; k < SLICEN * 2; k += TPB) sB4[k] = g_frag[tc][tb + (k >> 1)][k & 1];
    }
    __syncthreads();
    if (pruned) return;

    int gid = lane >> 2, tl = lane & 3;
    int lr = warp * 32 + gid;
    uint2 u0 = *reinterpret_cast<const uint2*>(&qA[lr +  0][2 * tl]);
    uint2 u1 = *reinterpret_cast<const uint2*>(&qA[lr +  8][2 * tl]);
    uint2 u2 = *reinterpret_cast<const uint2*>(&qA[lr + 16][2 * tl]);
    uint2 u3 = *reinterpret_cast<const uint2*>(&qA[lr + 24][2 * tl]);

    float ninf = __int_as_float(0xFF800000);
    float mx00 = ninf, mx01 = ninf, mx10 = ninf, mx11 = ninf;
    mma_sweep(reinterpret_cast<const uint2*>(sB4), SLICEN,
              u0.x, u1.x, u0.y, u1.y, u2.x, u3.x, u2.y, u3.y, gid, tl,
              mx00, mx01, mx10, mx11);

#pragma unroll
    for (int off = 1; off <= 2; off <<= 1) {
        mx00 = fmaxf(mx00, __shfl_xor_sync(0xffffffffu, mx00, off));
        mx01 = fmaxf(mx01, __shfl_xor_sync(0xffffffffu, mx01, off));
        mx10 = fmaxf(mx10, __shfl_xor_sync(0xffffffffu, mx10, off));
        mx11 = fmaxf(mx11, __shfl_xor_sync(0xffffffffu, mx11, off));
    }
    if (tl == 0) {
        atomicMin(&g_best[dir][sQid[lr +  0]], enc_f(fmaf(-2.f, mx00, sQsq[lr +  0])));
        atomicMin(&g_best[dir][sQid[lr +  8]], enc_f(fmaf(-2.f, mx01, sQsq[lr +  8])));
        atomicMin(&g_best[dir][sQid[lr + 16]], enc_f(fmaf(-2.f, mx10, sQsq[lr + 16])));
        atomicMin(&g_best[dir][sQid[lr + 24]], enc_f(fmaf(-2.f, mx11, sQsq[lr + 24])));
    }
}

// ============================================================================
// 6) fused reduction: block partial sums + last-block-ticket final sum.
// ============================================================================
__global__ void __launch_bounds__(TPB)
k_red(float* __restrict__ out) {
    __shared__ float sh[TPB];
    __shared__ int   amLast;
    int rid = blockIdx.x * TPB + threadIdx.x;
    int dir = rid >> 14, row = rid & (NPTS - 1);
    sh[threadIdx.x] = dec_f(g_best[dir][row]);
    __syncthreads();
    for (int k = TPB / 2; k > 0; k >>= 1) {
        if (threadIdx.x < k) sh[threadIdx.x] += sh[threadIdx.x + k];
        __syncthreads();
    }
    if (threadIdx.x == 0) {
        g_bsum[blockIdx.x] = sh[0];
        __threadfence();
        amLast = (atomicAdd(&g_ticket, 1u) == REDB - 1);
    }
    __syncthreads();
    if (amLast && threadIdx.x == 0) {
        float s = 0.f;
#pragma unroll
        for (int k = 0; k < REDB; k++) s += *((volatile float*)&g_bsum[k]);
        out[0] = s / (float)NPTS;
        g_ticket = 0;   // reset for next graph replay
    }
}

extern "C" void kernel_launch(void* const* d_in, const int* in_sizes, int n_in,
                              void* d_out, int out_size) {
    const float* adv = (const float*)d_in[0];
    const float* ori = (const float*)d_in[1];
    k_hist<<<2 * NPTS / 256, 256>>>(adv, ori);
    k_scan<<<1, 64>>>();
    k_scatter<<<2 * NPTS / 256, 256>>>(adv, ori);
    k_seed<<<2 * QT * SQUART, TPB>>>();
    k_sweep<<<2 * QT * NSLICE, TPB>>>();
    k_red<<<REDB, TPB>>>((float*)d_out);
}